// round 4
// baseline (speedup 1.0000x reference)
#include <cuda_runtime.h>

// ---------------------------------------------------------------------------
// StandGCN2: 2-layer GCN. N<=100096 nodes, F=128 -> 128 -> 64.
//   dinv = rsqrt(1 + indeg)
//   hs1  = dinv[r] * (x @ W1)           (self-loop seeds agg1)
//   agg1[d] += hs1[s]  over edges       (vector float4 atomics)
//   h1   = relu(dinv[r]*agg1 + b1)      (fused into GEMM2 A-load)
//   hs2  = dinv[r] * (h1 @ W2)          (seeds d_out)
//   d_out[d] += hs2[s] over edges
//   d_out = dinv[r]*d_out + b2
// GEMMs use packed fp32x2 FMA (fma.rn.f32x2) — 2 fp32 FMA per issue slot,
// beating the FFMA-3reg half-rate cap on sm_103a.
// ---------------------------------------------------------------------------

#define MAXN 100096

__device__ float g_deg[MAXN];
__device__ float g_dinv[MAXN];
__device__ __align__(16) float g_hs1[(size_t)MAXN * 128];
__device__ __align__(16) float g_agg1[(size_t)MAXN * 128];
__device__ __align__(16) float g_hs2[(size_t)MAXN * 64];

typedef unsigned long long u64;

#define FMA2(d, a, b) \
    asm("fma.rn.f32x2 %0, %1, %2, %3;" : "=l"(d) : "l"(a), "l"(b), "l"(d))

#define DUP2(d, x) \
    asm("mov.b64 %0, {%1, %1};" : "=l"(d) : "r"(__float_as_uint(x)))

__device__ __forceinline__ float2 u64_as_f2(u64 v) {
    float2 r;
    asm("mov.b64 {%0, %1}, %2;" : "=f"(r.x), "=f"(r.y) : "l"(v));
    return r;
}

// ---------------------------------------------------------------------------
// Degree / normalization
// ---------------------------------------------------------------------------
__global__ void k_deg_init(int n) {
    int i = blockIdx.x * blockDim.x + threadIdx.x;
    if (i < n) g_deg[i] = 1.0f;  // self-loop
}

__global__ void k_deg_acc(const int* __restrict__ dst, int e) {
    int i = blockIdx.x * blockDim.x + threadIdx.x;
    if (i < e) atomicAdd(&g_deg[dst[i]], 1.0f);
}

__global__ void k_dinv(int n) {
    int i = blockIdx.x * blockDim.x + threadIdx.x;
    if (i < n) g_dinv[i] = rsqrtf(g_deg[i]);
}

// ---------------------------------------------------------------------------
// GEMM1: hs1 = agg1 = dinv[r] * (X @ W1),  X:[M,128], W1:[128,128]
// Block 128x128, 256 threads, microtile 8x8 (4 row-pairs x 8 cols, f32x2).
// As stored k-major (transposed) so row-pairs load as ulonglong2.
// Double-buffered smem, K chunked by 16 (8 chunks).
// ---------------------------------------------------------------------------
__global__ __launch_bounds__(256, 2) void k_gemm1(const float* __restrict__ X,
                                                  const float* __restrict__ W,
                                                  int M) {
    __shared__ float As[2][16][128];  // [k][row]
    __shared__ float Bs[2][16][128];  // [k][col]

    const int tid = threadIdx.x;
    const int row0 = blockIdx.x * 128;
    const int tx = tid & 15, ty = tid >> 4;
    const int r0 = ty * 8, c0 = tx * 8;

    u64 acc[4][8];
#pragma unroll
    for (int i = 0; i < 4; i++)
#pragma unroll
        for (int j = 0; j < 8; j++) acc[i][j] = 0ull;

    float4 ra[2], rb[2];

    // --- staging helpers (manually inlined via lambdas) ---
    auto ldg = [&](int kc) {
#pragma unroll
        for (int l = 0; l < 2; l++) {
            int i = tid + l * 256;
            int r = i & 127, q4 = i >> 7;
            int gr = row0 + r;
            ra[l] = make_float4(0.f, 0.f, 0.f, 0.f);
            if (gr < M)
                ra[l] = reinterpret_cast<const float4*>(X)[(size_t)gr * 32 + kc * 4 + q4];
            rb[l] = reinterpret_cast<const float4*>(W)[(size_t)kc * 512 + i];
        }
    };
    auto sts = [&](int buf) {
#pragma unroll
        for (int l = 0; l < 2; l++) {
            int i = tid + l * 256;
            int r = i & 127, q4 = i >> 7;
            As[buf][q4 * 4 + 0][r] = ra[l].x;
            As[buf][q4 * 4 + 1][r] = ra[l].y;
            As[buf][q4 * 4 + 2][r] = ra[l].z;
            As[buf][q4 * 4 + 3][r] = ra[l].w;
            reinterpret_cast<float4*>(&Bs[buf][0][0])[i] = rb[l];
        }
    };

    ldg(0);
    sts(0);
    ldg(1);
    __syncthreads();

    for (int kc = 0; kc < 8; kc++) {
        const int cur = kc & 1;
        if (kc + 1 < 8) sts((kc + 1) & 1);
        if (kc + 2 < 8) ldg(kc + 2);
#pragma unroll
        for (int k = 0; k < 16; k++) {
            ulonglong2 a01 = *reinterpret_cast<const ulonglong2*>(&As[cur][k][r0]);
            ulonglong2 a23 = *reinterpret_cast<const ulonglong2*>(&As[cur][k][r0 + 4]);
            float4 bl = *reinterpret_cast<const float4*>(&Bs[cur][k][c0]);
            float4 bh = *reinterpret_cast<const float4*>(&Bs[cur][k][c0 + 4]);
            u64 ap[4] = {a01.x, a01.y, a23.x, a23.y};
            u64 bb[8];
            DUP2(bb[0], bl.x); DUP2(bb[1], bl.y); DUP2(bb[2], bl.z); DUP2(bb[3], bl.w);
            DUP2(bb[4], bh.x); DUP2(bb[5], bh.y); DUP2(bb[6], bh.z); DUP2(bb[7], bh.w);
#pragma unroll
            for (int rp = 0; rp < 4; rp++)
#pragma unroll
                for (int j = 0; j < 8; j++) FMA2(acc[rp][j], ap[rp], bb[j]);
        }
        __syncthreads();
    }

    // epilogue: acc[rp][j] = {row r0+2rp, row r0+2rp+1} at col c0+j
#pragma unroll
    for (int rp = 0; rp < 4; rp++) {
        int gre = row0 + r0 + 2 * rp;
        float2 p[8];
#pragma unroll
        for (int j = 0; j < 8; j++) p[j] = u64_as_f2(acc[rp][j]);
#pragma unroll
        for (int h = 0; h < 2; h++) {
            int gr = gre + h;
            if (gr >= M) break;
            float dv = g_dinv[gr];
            float4 v0, v1;
            if (h == 0) {
                v0 = make_float4(p[0].x, p[1].x, p[2].x, p[3].x);
                v1 = make_float4(p[4].x, p[5].x, p[6].x, p[7].x);
            } else {
                v0 = make_float4(p[0].y, p[1].y, p[2].y, p[3].y);
                v1 = make_float4(p[4].y, p[5].y, p[6].y, p[7].y);
            }
            v0.x *= dv; v0.y *= dv; v0.z *= dv; v0.w *= dv;
            v1.x *= dv; v1.y *= dv; v1.z *= dv; v1.w *= dv;
            *reinterpret_cast<float4*>(&g_hs1[(size_t)gr * 128 + c0]) = v0;
            *reinterpret_cast<float4*>(&g_hs1[(size_t)gr * 128 + c0 + 4]) = v1;
            *reinterpret_cast<float4*>(&g_agg1[(size_t)gr * 128 + c0]) = v0;
            *reinterpret_cast<float4*>(&g_agg1[(size_t)gr * 128 + c0 + 4]) = v1;
        }
    }
}

// ---------------------------------------------------------------------------
// Edge scatter 1: agg1[dst] += hs1[src].  One warp per edge (32 float4).
// ---------------------------------------------------------------------------
__global__ __launch_bounds__(256) void k_edge1(const int* __restrict__ src,
                                               const int* __restrict__ dst,
                                               int E) {
    int t = blockIdx.x * 256 + threadIdx.x;
    int e = t >> 5;
    if (e >= E) return;
    int j = t & 31;
    int s = src[e], d = dst[e];
    float4 v = *reinterpret_cast<const float4*>(&g_hs1[(size_t)s * 128 + j * 4]);
    atomicAdd(reinterpret_cast<float4*>(&g_agg1[(size_t)d * 128 + j * 4]), v);
}

// ---------------------------------------------------------------------------
// GEMM2: A[r][k] = relu(dinv[r]*agg1[r][k] + b1[k]) fused into the A-load;
//        hs2 = OUT = dinv[r] * (A @ W2),  W2:[128,64].
// Block 128x64, 256 threads, microtile 4x8 (4 rows x 4 col-pairs, f32x2).
// ---------------------------------------------------------------------------
__global__ __launch_bounds__(256, 2) void k_gemm2(const float* __restrict__ W2,
                                                  const float* __restrict__ B1,
                                                  float* __restrict__ OUT,
                                                  int M) {
    __shared__ float As[2][16][128];  // [k][row], fused relu(dinv*agg1+b1)
    __shared__ float Bs[2][16][64];   // [k][col]

    const int tid = threadIdx.x;
    const int row0 = blockIdx.x * 128;
    const int tx = tid & 7, ty = tid >> 3;
    const int r0 = ty * 4, c0 = tx * 8;

    u64 acc[4][4];
#pragma unroll
    for (int i = 0; i < 4; i++)
#pragma unroll
        for (int j = 0; j < 4; j++) acc[i][j] = 0ull;

    float4 ra[2], rb;

    auto ldg = [&](int kc) {
#pragma unroll
        for (int l = 0; l < 2; l++) {
            int i = tid + l * 256;
            int r = i & 127, q4 = i >> 7;
            int gr = row0 + r;
            float4 v = make_float4(0.f, 0.f, 0.f, 0.f);
            if (gr < M) {
                v = reinterpret_cast<const float4*>(g_agg1)[(size_t)gr * 32 + kc * 4 + q4];
                float dv = g_dinv[gr];
                float4 bv = reinterpret_cast<const float4*>(B1)[kc * 4 + q4];
                v.x = fmaxf(fmaf(dv, v.x, bv.x), 0.f);
                v.y = fmaxf(fmaf(dv, v.y, bv.y), 0.f);
                v.z = fmaxf(fmaf(dv, v.z, bv.z), 0.f);
                v.w = fmaxf(fmaf(dv, v.w, bv.w), 0.f);
            }
            ra[l] = v;
        }
        rb = reinterpret_cast<const float4*>(W2)[(size_t)kc * 256 + tid];
    };
    auto sts = [&](int buf) {
#pragma unroll
        for (int l = 0; l < 2; l++) {
            int i = tid + l * 256;
            int r = i & 127, q4 = i >> 7;
            As[buf][q4 * 4 + 0][r] = ra[l].x;
            As[buf][q4 * 4 + 1][r] = ra[l].y;
            As[buf][q4 * 4 + 2][r] = ra[l].z;
            As[buf][q4 * 4 + 3][r] = ra[l].w;
        }
        reinterpret_cast<float4*>(&Bs[buf][0][0])[tid] = rb;
    };

    ldg(0);
    sts(0);
    ldg(1);
    __syncthreads();

    for (int kc = 0; kc < 8; kc++) {
        const int cur = kc & 1;
        if (kc + 1 < 8) sts((kc + 1) & 1);
        if (kc + 2 < 8) ldg(kc + 2);
#pragma unroll
        for (int k = 0; k < 16; k++) {
            float4 a4 = *reinterpret_cast<const float4*>(&As[cur][k][r0]);
            ulonglong2 b01 = *reinterpret_cast<const ulonglong2*>(&Bs[cur][k][c0]);
            ulonglong2 b23 = *reinterpret_cast<const ulonglong2*>(&Bs[cur][k][c0 + 4]);
            u64 bp[4] = {b01.x, b01.y, b23.x, b23.y};
            u64 ad[4];
            DUP2(ad[0], a4.x); DUP2(ad[1], a4.y); DUP2(ad[2], a4.z); DUP2(ad[3], a4.w);
#pragma unroll
            for (int i = 0; i < 4; i++)
#pragma unroll
                for (int j = 0; j < 4; j++) FMA2(acc[i][j], ad[i], bp[j]);
        }
        __syncthreads();
    }

    // epilogue: acc[i][j] = cols {c0+2j, c0+2j+1} of row r0+i
#pragma unroll
    for (int i = 0; i < 4; i++) {
        int gr = row0 + r0 + i;
        if (gr >= M) break;
        float dv = g_dinv[gr];
        float2 p0 = u64_as_f2(acc[i][0]);
        float2 p1 = u64_as_f2(acc[i][1]);
        float2 p2 = u64_as_f2(acc[i][2]);
        float2 p3 = u64_as_f2(acc[i][3]);
        float4 v0 = make_float4(p0.x * dv, p0.y * dv, p1.x * dv, p1.y * dv);
        float4 v1 = make_float4(p2.x * dv, p2.y * dv, p3.x * dv, p3.y * dv);
        *reinterpret_cast<float4*>(&g_hs2[(size_t)gr * 64 + c0]) = v0;
        *reinterpret_cast<float4*>(&g_hs2[(size_t)gr * 64 + c0 + 4]) = v1;
        *reinterpret_cast<float4*>(&OUT[(size_t)gr * 64 + c0]) = v0;
        *reinterpret_cast<float4*>(&OUT[(size_t)gr * 64 + c0 + 4]) = v1;
    }
}

// ---------------------------------------------------------------------------
// Edge scatter 2: OUT[dst] += hs2[src].  Half-warp per edge (16 float4).
// ---------------------------------------------------------------------------
__global__ __launch_bounds__(256) void k_edge2(const int* __restrict__ src,
                                               const int* __restrict__ dst,
                                               float* __restrict__ OUT,
                                               int E) {
    int t = blockIdx.x * 256 + threadIdx.x;
    int e = t >> 4;
    if (e >= E) return;
    int j = t & 15;
    int s = src[e], d = dst[e];
    float4 v = *reinterpret_cast<const float4*>(&g_hs2[(size_t)s * 64 + j * 4]);
    atomicAdd(reinterpret_cast<float4*>(&OUT[(size_t)d * 64 + j * 4]), v);
}

// ---------------------------------------------------------------------------
// Final: OUT = dinv[row]*OUT + b2
// ---------------------------------------------------------------------------
__global__ void k_final(float* __restrict__ OUT, const float* __restrict__ B2, int M) {
    int t = blockIdx.x * blockDim.x + threadIdx.x;
    if (t >= M * 16) return;
    int row = t >> 4, q = t & 15;
    float dv = g_dinv[row];
    float4 v = reinterpret_cast<float4*>(OUT)[t];
    float4 b = reinterpret_cast<const float4*>(B2)[q];
    v.x = fmaf(dv, v.x, b.x);
    v.y = fmaf(dv, v.y, b.y);
    v.z = fmaf(dv, v.z, b.z);
    v.w = fmaf(dv, v.w, b.w);
    reinterpret_cast<float4*>(OUT)[t] = v;
}

// ---------------------------------------------------------------------------
extern "C" void kernel_launch(void* const* d_in, const int* in_sizes, int n_in,
                              void* d_out, int out_size) {
    const float* x  = (const float*)d_in[0];
    const int*   ei = (const int*)d_in[1];
    const float* W1 = (const float*)d_in[2];
    const float* b1 = (const float*)d_in[3];
    const float* W2 = (const float*)d_in[4];
    const float* b2 = (const float*)d_in[5];
    float* out = (float*)d_out;

    const int N = in_sizes[0] / 128;
    const int E = in_sizes[1] / 2;
    const int* src = ei;
    const int* dst = ei + E;

    k_deg_init<<<(N + 255) / 256, 256>>>(N);
    k_deg_acc<<<(E + 255) / 256, 256>>>(dst, E);
    k_dinv<<<(N + 255) / 256, 256>>>(N);

    k_gemm1<<<(N + 127) / 128, 256>>>(x, W1, N);

    {
        long long T = (long long)E * 32;
        k_edge1<<<(int)((T + 255) / 256), 256>>>(src, dst, E);
    }

    k_gemm2<<<(N + 127) / 128, 256>>>(W2, b1, out, N);

    {
        long long T = (long long)E * 16;
        k_edge2<<<(int)((T + 255) / 256), 256>>>(src, dst, out, E);
    }

    {
        long long T = (long long)N * 16;
        k_final<<<(int)((T + 255) / 256), 256>>>(out, b2, N);
    }
}

// round 5
// speedup vs baseline: 1.0919x; 1.0919x over previous
#include <cuda_runtime.h>

// ---------------------------------------------------------------------------
// StandGCN2: 2-layer GCN. N<=100096 nodes, F=128 -> 128 -> 64.
//
//   dinv = rsqrt(1 + indeg)
//   hs1  = dinv[r] * (x @ W1)                       (GEMM1, f32x2 FMA)
//   agg1[d] = hs1[d] + sum_{edges d} hs1[src]       (bucketed smem scatter)
//   h1   = relu(dinv[r]*agg1 + b1)                  (fused into GEMM2 A-load)
//   hs2  = dinv[r] * (h1 @ W2)                      (GEMM2)
//   OUT[d] = dinv[d]*(hs2[d] + sum hs2[src]) + b2   (bucketed scatter + fused
//                                                    final epilogue)
//
// Edges are counting-sorted by dst>>4 (16-node buckets). One warp owns one
// bucket with a private smem accumulator tile; lanes own disjoint feature
// slices -> no atomics anywhere in the feature scatter.
// ---------------------------------------------------------------------------

#define MAXN 100096
#define MAXB (MAXN / 16)      // 6256 buckets
#define MAXE 1200000

__device__ float g_deg[MAXN];
__device__ float g_dinv[MAXN];
__device__ __align__(16) float g_hs1[(size_t)MAXN * 128];
__device__ __align__(16) float g_agg1[(size_t)MAXN * 128];
__device__ __align__(16) float g_hs2[(size_t)MAXN * 64];

__device__ int g_esrc[MAXE];
__device__ int g_edst[MAXE];
__device__ int g_bstart[MAXB + 1];
__device__ int g_bcur[MAXB];

typedef unsigned long long u64;

#define FMA2(d, a, b) \
    asm("fma.rn.f32x2 %0, %1, %2, %3;" : "=l"(d) : "l"(a), "l"(b), "l"(d))

#define DUP2(d, x) \
    asm("mov.b64 %0, {%1, %1};" : "=l"(d) : "r"(__float_as_uint(x)))

__device__ __forceinline__ float2 u64_as_f2(u64 v) {
    float2 r;
    asm("mov.b64 {%0, %1}, %2;" : "=f"(r.x), "=f"(r.y) : "l"(v));
    return r;
}

// ---------------------------------------------------------------------------
// Init: deg=1 (self-loop), bucket histogram = 0
// ---------------------------------------------------------------------------
__global__ void k_init(int n, int nb) {
    int i = blockIdx.x * blockDim.x + threadIdx.x;
    if (i < n) g_deg[i] = 1.0f;
    if (i < nb) g_bcur[i] = 0;
}

// Degree + bucket histogram in one pass over dst
__global__ void k_count(const int* __restrict__ dst, int e) {
    int i = blockIdx.x * blockDim.x + threadIdx.x;
    if (i >= e) return;
    int d = dst[i];
    atomicAdd(&g_deg[d], 1.0f);
    atomicAdd(&g_bcur[d >> 4], 1);
}

__global__ void k_dinv(int n) {
    int i = blockIdx.x * blockDim.x + threadIdx.x;
    if (i < n) g_dinv[i] = rsqrtf(g_deg[i]);
}

// Exclusive scan of bucket counts -> g_bstart; reset g_bcur to start offsets.
// Single block, 1024 threads, chunked Hillis-Steele.
__global__ void k_scan(int nb) {
    __shared__ int sbuf[1024];
    __shared__ int scarry;
    int t = threadIdx.x;
    if (t == 0) scarry = 0;
    __syncthreads();
    for (int base = 0; base < nb; base += 1024) {
        int idx = base + t;
        int v = (idx < nb) ? g_bcur[idx] : 0;
        sbuf[t] = v;
        __syncthreads();
        for (int off = 1; off < 1024; off <<= 1) {
            int x = (t >= off) ? sbuf[t - off] : 0;
            __syncthreads();
            sbuf[t] += x;
            __syncthreads();
        }
        int incl = sbuf[t];
        int total = sbuf[1023];
        int excl = incl - v + scarry;
        if (idx < nb) {
            g_bstart[idx] = excl;
            g_bcur[idx] = excl;
        }
        __syncthreads();
        if (t == 0) scarry += total;
        __syncthreads();
    }
    if (t == 0) g_bstart[nb] = scarry;
}

// Scatter edges into bucket-sorted order
__global__ void k_sort(const int* __restrict__ src, const int* __restrict__ dst,
                       int e) {
    int i = blockIdx.x * blockDim.x + threadIdx.x;
    if (i >= e) return;
    int s = src[i], d = dst[i];
    int pos = atomicAdd(&g_bcur[d >> 4], 1);
    g_esrc[pos] = s;
    g_edst[pos] = d;
}

// ---------------------------------------------------------------------------
// GEMM1: hs1 = dinv[r] * (X @ W1),  X:[M,128], W1:[128,128]
// Block 128x128, 256 threads, microtile 8x8 via f32x2. Double-buffered.
// ---------------------------------------------------------------------------
__global__ __launch_bounds__(256, 2) void k_gemm1(const float* __restrict__ X,
                                                  const float* __restrict__ W,
                                                  int M) {
    __shared__ float As[2][16][128];  // [k][row]
    __shared__ float Bs[2][16][128];  // [k][col]

    const int tid = threadIdx.x;
    const int row0 = blockIdx.x * 128;
    const int tx = tid & 15, ty = tid >> 4;
    const int r0 = ty * 8, c0 = tx * 8;

    u64 acc[4][8];
#pragma unroll
    for (int i = 0; i < 4; i++)
#pragma unroll
        for (int j = 0; j < 8; j++) acc[i][j] = 0ull;

    float4 ra[2], rb[2];

    auto ldg = [&](int kc) {
#pragma unroll
        for (int l = 0; l < 2; l++) {
            int i = tid + l * 256;
            int r = i & 127, q4 = i >> 7;
            int gr = row0 + r;
            ra[l] = make_float4(0.f, 0.f, 0.f, 0.f);
            if (gr < M)
                ra[l] = reinterpret_cast<const float4*>(X)[(size_t)gr * 32 + kc * 4 + q4];
            rb[l] = reinterpret_cast<const float4*>(W)[(size_t)kc * 512 + i];
        }
    };
    auto sts = [&](int buf) {
#pragma unroll
        for (int l = 0; l < 2; l++) {
            int i = tid + l * 256;
            int r = i & 127, q4 = i >> 7;
            As[buf][q4 * 4 + 0][r] = ra[l].x;
            As[buf][q4 * 4 + 1][r] = ra[l].y;
            As[buf][q4 * 4 + 2][r] = ra[l].z;
            As[buf][q4 * 4 + 3][r] = ra[l].w;
            reinterpret_cast<float4*>(&Bs[buf][0][0])[i] = rb[l];
        }
    };

    ldg(0);
    sts(0);
    ldg(1);
    __syncthreads();

    for (int kc = 0; kc < 8; kc++) {
        const int cur = kc & 1;
        if (kc + 1 < 8) sts((kc + 1) & 1);
        if (kc + 2 < 8) ldg(kc + 2);
#pragma unroll
        for (int k = 0; k < 16; k++) {
            ulonglong2 a01 = *reinterpret_cast<const ulonglong2*>(&As[cur][k][r0]);
            ulonglong2 a23 = *reinterpret_cast<const ulonglong2*>(&As[cur][k][r0 + 4]);
            float4 bl = *reinterpret_cast<const float4*>(&Bs[cur][k][c0]);
            float4 bh = *reinterpret_cast<const float4*>(&Bs[cur][k][c0 + 4]);
            u64 ap[4] = {a01.x, a01.y, a23.x, a23.y};
            u64 bb[8];
            DUP2(bb[0], bl.x); DUP2(bb[1], bl.y); DUP2(bb[2], bl.z); DUP2(bb[3], bl.w);
            DUP2(bb[4], bh.x); DUP2(bb[5], bh.y); DUP2(bb[6], bh.z); DUP2(bb[7], bh.w);
#pragma unroll
            for (int rp = 0; rp < 4; rp++)
#pragma unroll
                for (int j = 0; j < 8; j++) FMA2(acc[rp][j], ap[rp], bb[j]);
        }
        __syncthreads();
    }

#pragma unroll
    for (int rp = 0; rp < 4; rp++) {
        int gre = row0 + r0 + 2 * rp;
        float2 p[8];
#pragma unroll
        for (int j = 0; j < 8; j++) p[j] = u64_as_f2(acc[rp][j]);
#pragma unroll
        for (int h = 0; h < 2; h++) {
            int gr = gre + h;
            if (gr >= M) break;
            float dv = g_dinv[gr];
            float4 v0, v1;
            if (h == 0) {
                v0 = make_float4(p[0].x, p[1].x, p[2].x, p[3].x);
                v1 = make_float4(p[4].x, p[5].x, p[6].x, p[7].x);
            } else {
                v0 = make_float4(p[0].y, p[1].y, p[2].y, p[3].y);
                v1 = make_float4(p[4].y, p[5].y, p[6].y, p[7].y);
            }
            v0.x *= dv; v0.y *= dv; v0.z *= dv; v0.w *= dv;
            v1.x *= dv; v1.y *= dv; v1.z *= dv; v1.w *= dv;
            *reinterpret_cast<float4*>(&g_hs1[(size_t)gr * 128 + c0]) = v0;
            *reinterpret_cast<float4*>(&g_hs1[(size_t)gr * 128 + c0 + 4]) = v1;
        }
    }
}

// ---------------------------------------------------------------------------
// Edge aggregate 1: agg1[d] = hs1[d] + sum hs1[src], bucketed, no atomics.
// 128 threads = 4 warps; warp w owns bucket blk*4+w (16 nodes x 128 feats).
// Lane l owns float4 feature slice [4l, 4l+4).
// ---------------------------------------------------------------------------
__global__ __launch_bounds__(128) void k_edge1(int n, int nb) {
    __shared__ __align__(16) float acc[4][16][128];  // 32 KB

    const int w = threadIdx.x >> 5;
    const int l4 = (threadIdx.x & 31) * 4;
    const int b = blockIdx.x * 4 + w;
    if (b >= nb) return;
    const int n0 = b * 16;

    // seed with self-loop rows
#pragma unroll
    for (int r = 0; r < 16; r++) {
        int node = n0 + r;
        float4 v = make_float4(0.f, 0.f, 0.f, 0.f);
        if (node < n)
            v = *reinterpret_cast<const float4*>(&g_hs1[(size_t)node * 128 + l4]);
        *reinterpret_cast<float4*>(&acc[w][r][l4]) = v;
    }

    int e = g_bstart[b];
    const int e1 = g_bstart[b + 1];
    for (; e + 3 < e1; e += 4) {
        int s0 = g_esrc[e],     d0 = g_edst[e];
        int s1 = g_esrc[e + 1], d1 = g_edst[e + 1];
        int s2 = g_esrc[e + 2], d2 = g_edst[e + 2];
        int s3 = g_esrc[e + 3], d3 = g_edst[e + 3];
        float4 v0 = *reinterpret_cast<const float4*>(&g_hs1[(size_t)s0 * 128 + l4]);
        float4 v1 = *reinterpret_cast<const float4*>(&g_hs1[(size_t)s1 * 128 + l4]);
        float4 v2 = *reinterpret_cast<const float4*>(&g_hs1[(size_t)s2 * 128 + l4]);
        float4 v3 = *reinterpret_cast<const float4*>(&g_hs1[(size_t)s3 * 128 + l4]);
        float4* a;
        float4 o;
        a = reinterpret_cast<float4*>(&acc[w][d0 - n0][l4]); o = *a;
        o.x += v0.x; o.y += v0.y; o.z += v0.z; o.w += v0.w; *a = o;
        a = reinterpret_cast<float4*>(&acc[w][d1 - n0][l4]); o = *a;
        o.x += v1.x; o.y += v1.y; o.z += v1.z; o.w += v1.w; *a = o;
        a = reinterpret_cast<float4*>(&acc[w][d2 - n0][l4]); o = *a;
        o.x += v2.x; o.y += v2.y; o.z += v2.z; o.w += v2.w; *a = o;
        a = reinterpret_cast<float4*>(&acc[w][d3 - n0][l4]); o = *a;
        o.x += v3.x; o.y += v3.y; o.z += v3.z; o.w += v3.w; *a = o;
    }
    for (; e < e1; e++) {
        int s = g_esrc[e], d = g_edst[e];
        float4 v = *reinterpret_cast<const float4*>(&g_hs1[(size_t)s * 128 + l4]);
        float4* a = reinterpret_cast<float4*>(&acc[w][d - n0][l4]);
        float4 o = *a;
        o.x += v.x; o.y += v.y; o.z += v.z; o.w += v.w;
        *a = o;
    }

#pragma unroll
    for (int r = 0; r < 16; r++) {
        int node = n0 + r;
        if (node < n)
            *reinterpret_cast<float4*>(&g_agg1[(size_t)node * 128 + l4]) =
                *reinterpret_cast<const float4*>(&acc[w][r][l4]);
    }
}

// ---------------------------------------------------------------------------
// GEMM2: A[r][k] = relu(dinv[r]*agg1[r][k] + b1[k]) (fused on load)
//        hs2 = dinv[r] * (A @ W2),  W2: [128,64]
// Block 64x64, 256 threads, thread tile 4x4 (R3 version, hs2-only write).
// ---------------------------------------------------------------------------
__global__ __launch_bounds__(256) void k_gemm2(const float* __restrict__ W2,
                                               const float* __restrict__ B1,
                                               int M) {
    __shared__ float As[64][33];
    __shared__ float Bs[32][64];

    const int tid = threadIdx.x;
    const int row0 = blockIdx.x * 64;
    const int tx = tid & 15, ty = tid >> 4;
    const int r0 = ty * 4, c0 = tx * 4;

    float acc[4][4];
#pragma unroll
    for (int i = 0; i < 4; i++)
#pragma unroll
        for (int j = 0; j < 4; j++) acc[i][j] = 0.f;

    for (int kc = 0; kc < 4; kc++) {
#pragma unroll
        for (int l = 0; l < 2; l++) {
            int i = tid + l * 256;
            int r = i >> 3, q = i & 7;
            int gr = row0 + r;
            float4 v = make_float4(0.f, 0.f, 0.f, 0.f);
            if (gr < M) {
                v = reinterpret_cast<const float4*>(g_agg1)[(size_t)gr * 32 + kc * 8 + q];
                float dv = g_dinv[gr];
                int kb = kc * 32 + q * 4;
                v.x = fmaxf(fmaf(dv, v.x, B1[kb + 0]), 0.f);
                v.y = fmaxf(fmaf(dv, v.y, B1[kb + 1]), 0.f);
                v.z = fmaxf(fmaf(dv, v.z, B1[kb + 2]), 0.f);
                v.w = fmaxf(fmaf(dv, v.w, B1[kb + 3]), 0.f);
            }
            As[r][q * 4 + 0] = v.x;
            As[r][q * 4 + 1] = v.y;
            As[r][q * 4 + 2] = v.z;
            As[r][q * 4 + 3] = v.w;
        }
#pragma unroll
        for (int l = 0; l < 2; l++) {
            int i = tid + l * 256;
            reinterpret_cast<float4*>(&Bs[0][0])[i] =
                reinterpret_cast<const float4*>(W2 + (size_t)kc * 32 * 64)[i];
        }
        __syncthreads();

#pragma unroll
        for (int k = 0; k < 32; k++) {
            float a[4];
#pragma unroll
            for (int i = 0; i < 4; i++) a[i] = As[r0 + i][k];
            float4 b4 = *reinterpret_cast<float4*>(&Bs[k][c0]);
            float b[4] = {b4.x, b4.y, b4.z, b4.w};
#pragma unroll
            for (int i = 0; i < 4; i++)
#pragma unroll
                for (int j = 0; j < 4; j++) acc[i][j] = fmaf(a[i], b[j], acc[i][j]);
        }
        __syncthreads();
    }

#pragma unroll
    for (int i = 0; i < 4; i++) {
        int gr = row0 + r0 + i;
        if (gr >= M) break;
        float dv = g_dinv[gr];
        float4 v;
        v.x = acc[i][0] * dv;
        v.y = acc[i][1] * dv;
        v.z = acc[i][2] * dv;
        v.w = acc[i][3] * dv;
        *reinterpret_cast<float4*>(&g_hs2[(size_t)gr * 64 + c0]) = v;
    }
}

// ---------------------------------------------------------------------------
// Edge aggregate 2 + final epilogue:
//   OUT[d] = dinv[d] * (hs2[d] + sum hs2[src]) + b2
// Warp per 16-node bucket, lane l owns float2 slice [2l, 2l+2) of 64 feats.
// ---------------------------------------------------------------------------
__global__ __launch_bounds__(128) void k_edge2(float* __restrict__ OUT,
                                               const float* __restrict__ B2,
                                               int n, int nb) {
    __shared__ __align__(8) float acc[4][16][64];  // 16 KB

    const int w = threadIdx.x >> 5;
    const int l2 = (threadIdx.x & 31) * 2;
    const int b = blockIdx.x * 4 + w;
    if (b >= nb) return;
    const int n0 = b * 16;

#pragma unroll
    for (int r = 0; r < 16; r++) {
        int node = n0 + r;
        float2 v = make_float2(0.f, 0.f);
        if (node < n)
            v = *reinterpret_cast<const float2*>(&g_hs2[(size_t)node * 64 + l2]);
        *reinterpret_cast<float2*>(&acc[w][r][l2]) = v;
    }

    int e = g_bstart[b];
    const int e1 = g_bstart[b + 1];
    for (; e + 3 < e1; e += 4) {
        int s0 = g_esrc[e],     d0 = g_edst[e];
        int s1 = g_esrc[e + 1], d1 = g_edst[e + 1];
        int s2 = g_esrc[e + 2], d2 = g_edst[e + 2];
        int s3 = g_esrc[e + 3], d3 = g_edst[e + 3];
        float2 v0 = *reinterpret_cast<const float2*>(&g_hs2[(size_t)s0 * 64 + l2]);
        float2 v1 = *reinterpret_cast<const float2*>(&g_hs2[(size_t)s1 * 64 + l2]);
        float2 v2 = *reinterpret_cast<const float2*>(&g_hs2[(size_t)s2 * 64 + l2]);
        float2 v3 = *reinterpret_cast<const float2*>(&g_hs2[(size_t)s3 * 64 + l2]);
        float2* a;
        float2 o;
        a = reinterpret_cast<float2*>(&acc[w][d0 - n0][l2]); o = *a;
        o.x += v0.x; o.y += v0.y; *a = o;
        a = reinterpret_cast<float2*>(&acc[w][d1 - n0][l2]); o = *a;
        o.x += v1.x; o.y += v1.y; *a = o;
        a = reinterpret_cast<float2*>(&acc[w][d2 - n0][l2]); o = *a;
        o.x += v2.x; o.y += v2.y; *a = o;
        a = reinterpret_cast<float2*>(&acc[w][d3 - n0][l2]); o = *a;
        o.x += v3.x; o.y += v3.y; *a = o;
    }
    for (; e < e1; e++) {
        int s = g_esrc[e], d = g_edst[e];
        float2 v = *reinterpret_cast<const float2*>(&g_hs2[(size_t)s * 64 + l2]);
        float2* a = reinterpret_cast<float2*>(&acc[w][d - n0][l2]);
        float2 o = *a;
        o.x += v.x; o.y += v.y;
        *a = o;
    }

    float2 bb = *reinterpret_cast<const float2*>(&B2[l2]);
#pragma unroll
    for (int r = 0; r < 16; r++) {
        int node = n0 + r;
        if (node < n) {
            float dv = g_dinv[node];
            float2 o = *reinterpret_cast<const float2*>(&acc[w][r][l2]);
            o.x = fmaf(dv, o.x, bb.x);
            o.y = fmaf(dv, o.y, bb.y);
            *reinterpret_cast<float2*>(&OUT[(size_t)node * 64 + l2]) = o;
        }
    }
}

// ---------------------------------------------------------------------------
extern "C" void kernel_launch(void* const* d_in, const int* in_sizes, int n_in,
                              void* d_out, int out_size) {
    const float* x  = (const float*)d_in[0];
    const int*   ei = (const int*)d_in[1];
    const float* W1 = (const float*)d_in[2];
    const float* b1 = (const float*)d_in[3];
    const float* W2 = (const float*)d_in[4];
    const float* b2 = (const float*)d_in[5];
    float* out = (float*)d_out;

    const int N = in_sizes[0] / 128;
    const int E = in_sizes[1] / 2;
    const int NB = (N + 15) / 16;
    const int* src = ei;
    const int* dst = ei + E;

    int mx = (N > NB) ? N : NB;
    k_init<<<(mx + 255) / 256, 256>>>(N, NB);
    k_count<<<(E + 255) / 256, 256>>>(dst, E);
    k_dinv<<<(N + 255) / 256, 256>>>(N);
    k_scan<<<1, 1024>>>(NB);
    k_sort<<<(E + 255) / 256, 256>>>(src, dst, E);

    k_gemm1<<<(N + 127) / 128, 256>>>(x, W1, N);
    k_edge1<<<(NB + 3) / 4, 128>>>(N, NB);
    k_gemm2<<<(N + 63) / 64, 256>>>(W2, b1, N);
    k_edge2<<<(NB + 3) / 4, 128>>>(out, b2, N, NB);
}